// round 9
// baseline (speedup 1.0000x reference)
#include <cuda_runtime.h>
#include <math.h>

// Problem constants
#define B_  2
#define C_  64
#define H_  128
#define W_  128
#define HW_ (H_*W_)          // 16384
#define HID 16
#define OFC 18
#define NPT 9
#define KTOT (C_*NPT)        // 576
#define PIXT (B_*HW_)        // 32768
#define HP_  130
#define WP_  130
#define HWP_ (HP_*WP_)       // 16900

// ---- device scratch (no runtime allocation allowed) ----
__device__ float g_f  [B_*HID*HW_];       // offset-branch feature [B,16,H,W]
__device__ float g_off[B_*OFC*HW_];       // offsets               [B,18,H,W]
__device__ float g_wt2[288*128];          // k-pair-packed w_out (see k_padT)
__device__ float g_xp [B_*HWP_*C_ + 8];   // TRANSPOSED padded input [B][130*130][64]

// packed fp32x2 FMA (per-component accumulate: pairs carry adjacent k)
#define FMA2(d,a,b) asm("fma.rn.f32x2 %0, %1, %2, %0;" : "+l"(d) : "l"(a), "l"(b))

// ============================================================
// K_padT: zero-pad + TRANSPOSE x into g_xp[b][hw_p][c]
//   tail blocks: pack w_out into g_wt2:
//     k-global = n*64 + ci  (chunk n, channel ci), k-pair kp = n*32 + (ci>>1)
//     row kp (128 floats) = [A-half 64 | B-half 64]:
//       A-half: oc groups j=0,1  -> col = (oc>>2)*4 + j*2 + (ci&1)
//       B-half: oc groups j=2,3  -> col = 64 + (oc>>2)*4 + (j-2)*2 + (ci&1)
// ============================================================
#define PAD_BLKS (B_*HP_)
#define W0_BLKS  ((KTOT*C_ + 255)/256)
__global__ __launch_bounds__(256)
void k_padT(const float* __restrict__ x, const float* __restrict__ w) {
    int blk = blockIdx.x;
    int tid = threadIdx.x;
    if (blk < PAD_BLKS) {
        __shared__ float ts[WP_ * 65];     // [w][c] pitch 65 (conflict-free)
        int b = blk / HP_, h = blk % HP_;
        if (h >= 1 && h <= H_) {
            const float* xr = x + (size_t)b * C_ * HW_ + (h - 1) * W_;
            for (int e = tid; e < C_ * W_; e += 256) {
                int c = e >> 7, w2 = e & 127;            // coalesced read along w
                ts[(w2 + 1) * 65 + c] = xr[c * HW_ + w2];
            }
            if (tid < 2 * C_) {                          // border columns
                int c = tid & 63, side = tid >> 6;
                ts[(side ? (WP_ - 1) * 65 : 0) + c] = 0.f;
            }
        } else {
            for (int e = tid; e < WP_ * C_; e += 256) {
                int w2 = e >> 6, c = e & 63;
                ts[w2 * 65 + c] = 0.f;
            }
        }
        __syncthreads();
        float* dst = g_xp + ((size_t)b * HP_ + h) * WP_ * C_;
        for (int e = tid; e < WP_ * C_; e += 256) {
            int w2 = e >> 6, c = e & 63;
            dst[e] = ts[w2 * 65 + c];                    // coalesced write along c
        }
    } else {
        int t = (blk - PAD_BLKS) * 256 + tid;
        if (t < KTOT * C_) {
            int oc = t / KTOT, r = t - oc * KTOT;        // r = ci*9 + n
            int ci = r / 9, n = r - ci * 9;
            int kp = n * 32 + (ci >> 1);
            int q  = ci & 1;
            int tq = oc >> 2, j = oc & 3;
            int col = (j < 2) ? (tq * 4 + j * 2 + q)
                              : (64 + tq * 4 + (j - 2) * 2 + q);
            g_wt2[kp * 128 + col] = w[t];
        }
    }
}

// ============================================================
// K1: f = relu(bn(conv1x1_{64->16}(x)))
// ============================================================
__global__ void k1_conv1(const float* __restrict__ x,
                         const float* __restrict__ w1,
                         const float* __restrict__ g1,
                         const float* __restrict__ b1,
                         const float* __restrict__ m1,
                         const float* __restrict__ v1) {
    __shared__ float ws[C_][HID];
    __shared__ float inv_s[HID], beta_s[HID];
    int tid = threadIdx.x;
    for (int e = tid; e < HID * C_; e += 256) {
        int o = e / C_, c = e % C_;
        ws[c][o] = w1[e];
    }
    if (tid < HID) {
        float inv = g1[tid] * rsqrtf(v1[tid] + 1e-5f);
        inv_s[tid] = inv;
        beta_s[tid] = b1[tid] - m1[tid] * inv;
    }
    __syncthreads();

    int p = blockIdx.x * 256 + tid;
    int b = p >> 14, hw = p & (HW_ - 1);
    const float* xb = x + (size_t)b * C_ * HW_ + hw;

    float acc[HID];
#pragma unroll
    for (int o = 0; o < HID; o++) acc[o] = 0.f;
    for (int c = 0; c < C_; c++) {
        float xv = xb[c * HW_];
#pragma unroll
        for (int o = 0; o < HID; o++) acc[o] += ws[c][o] * xv;
    }
    float* fb = g_f + (size_t)b * HID * HW_ + hw;
#pragma unroll
    for (int o = 0; o < HID; o++)
        fb[o * HW_] = fmaxf(acc[o] * inv_s[o] + beta_s[o], 0.f);
}

// ============================================================
// K2 (tiled): off = relu(bn3(1x1( relu(bn2(3x3(f))) )))
// ============================================================
__global__ __launch_bounds__(256)
void k2_offsets(const float* __restrict__ wdw,
                const float* __restrict__ g2, const float* __restrict__ b2,
                const float* __restrict__ m2, const float* __restrict__ v2,
                const float* __restrict__ wc2,
                const float* __restrict__ g3, const float* __restrict__ b3,
                const float* __restrict__ m3, const float* __restrict__ v3) {
    __shared__ float fs[HID * 18 * 18];
    __shared__ float wdw_s[OFC * HID * 9];
    __shared__ float wc2_s[OFC * OFC];
    __shared__ float inv2_s[OFC], beta2_s[OFC], inv3_s[OFC], beta3_s[OFC];
    int tid = threadIdx.x;

    int blk = blockIdx.x;
    int b = blk >> 6, t = blk & 63;
    int h0 = (t >> 3) << 4, w0 = (t & 7) << 4;

    for (int e = tid; e < OFC * HID * 9; e += 256) wdw_s[e] = wdw[e];
    for (int e = tid; e < OFC * OFC; e += 256)     wc2_s[e] = wc2[e];
    if (tid < OFC) {
        float i2 = g2[tid] * rsqrtf(v2[tid] + 1e-5f);
        inv2_s[tid] = i2; beta2_s[tid] = b2[tid] - m2[tid] * i2;
        float i3 = g3[tid] * rsqrtf(v3[tid] + 1e-5f);
        inv3_s[tid] = i3; beta3_s[tid] = b3[tid] - m3[tid] * i3;
    }

    const float* fb = g_f + (size_t)b * HID * HW_;
    for (int e = tid; e < HID * 324; e += 256) {
        int ci = e / 324, r = e - ci * 324;
        int hh = r / 18, ww = r - hh * 18;
        int h = h0 - 1 + hh, w = w0 - 1 + ww;
        float v = 0.f;
        if (h >= 0 && h < H_ && w >= 0 && w < W_)
            v = fb[ci * HW_ + h * W_ + w];
        fs[e] = v;
    }
    __syncthreads();

    int ty2 = tid >> 4, tx2 = tid & 15;
    float acc[OFC];
#pragma unroll
    for (int o = 0; o < OFC; o++) acc[o] = 0.f;

    for (int ci = 0; ci < HID; ci++) {
        float fv[9];
        const float* fsc = fs + ci * 324;
#pragma unroll
        for (int dh = 0; dh < 3; dh++)
#pragma unroll
            for (int dw = 0; dw < 3; dw++)
                fv[dh * 3 + dw] = fsc[(ty2 + dh) * 18 + (tx2 + dw)];
        const float* wp = wdw_s + ci * 9;
#pragma unroll
        for (int o = 0; o < OFC; o++) {
            const float* wo = wp + o * (HID * 9);
            float a = acc[o];
#pragma unroll
            for (int k = 0; k < 9; k++) a += wo[k] * fv[k];
            acc[o] = a;
        }
    }
    float tv[OFC];
#pragma unroll
    for (int o = 0; o < OFC; o++)
        tv[o] = fmaxf(acc[o] * inv2_s[o] + beta2_s[o], 0.f);

    int h = h0 + ty2, w = w0 + tx2;
    float* op = g_off + (size_t)b * OFC * HW_ + h * W_ + w;
#pragma unroll
    for (int o2 = 0; o2 < OFC; o2++) {
        float a = 0.f;
#pragma unroll
        for (int o = 0; o < OFC; o++) a += wc2_s[o2 * OFC + o] * tv[o];
        op[o2 * HW_] = fmaxf(a * inv3_s[o2] + beta3_s[o2], 0.f);
    }
}

// ============================================================
// K3: fused bilinear sampler + SGEMM, k-paired f32x2 (NO duplication)
//   chunk = sampling point n (9 chunks of 64 k = 64 channels)
//   gather: warp = 1 sample x 64 ch, lane = 2 ch  -> contiguous STS
//   slab: a[64 px][68] non-dup, double-buffered
//   thread tile: 4 px x 4 oc, acc = f32x2 k-partials (lo+hi at end)
// ============================================================
#define APITCH 68
#define SLABN (64*APITCH)
#define K3_SMEM (576*32 + 2*SLABN*4)   // 18432 + 34816 = 53248

__global__ __launch_bounds__(256, 3)
void k3_main(const float* __restrict__ x, float* __restrict__ out) {
    extern __shared__ char smem[];
    int4*   idx_s = (int4*)smem;                   // [576] (n*64+m), premult by 64
    float4* wgt_s = (float4*)(smem + 9216);        // [576]
    float*  slab  = (float*)(smem + 18432);        // [2][64][APITCH]

    int tid = threadIdx.x;
    int blk = blockIdx.x;
    int b = blk >> 8;
    int tile = blk & 255;
    int h0 = (tile >> 4) << 3;
    int w0 = (tile & 15) << 3;

    // ---- bilinear metadata: 64 px x 9 pts ----
    const float* offp = g_off + (size_t)b * OFC * HW_;
    for (int e = tid; e < 64 * NPT; e += 256) {
        int m = e / NPT, n = e - m * NPT;
        int h = h0 + (m >> 3), w = w0 + (m & 7);
        int hw = h * W_ + w;
        float offx = offp[n * HW_ + hw];
        float offy = offp[(NPT + n) * HW_ + hw];
        float px = (float)(h + 1) + (float)(n / 3 - 1) + offx;
        float py = (float)(w + 1) + (float)(n % 3 - 1) + offy;
        float flx = floorf(px), fly = floorf(py);
        float qltx = fminf(fmaxf(flx, 0.f), 129.f);
        float qlty = fminf(fmaxf(fly, 0.f), 129.f);
        float qrbx = fminf(fmaxf(flx + 1.f, 0.f), 129.f);
        float qrby = fminf(fmaxf(fly + 1.f, 0.f), 129.f);
        px = fminf(fmaxf(px, 0.f), 129.f);
        py = fminf(fmaxf(py, 0.f), 129.f);
        float gxl = 1.f + qltx - px, gxr = 1.f - qrbx + px;
        float gyl = 1.f + qlty - py, gyr = 1.f - qrby + py;
        float4 g;
        g.x = gxl * gyl; g.y = gxr * gyr; g.z = gxl * gyr; g.w = gxr * gyl;
        int ltx = (int)qltx, lty = (int)qlty, rbx = (int)qrbx, rby = (int)qrby;
        int4 id;
        id.x = (ltx * WP_ + lty) << 6;    // premultiplied by C_=64
        id.y = (rbx * WP_ + rby) << 6;
        id.z = (ltx * WP_ + rby) << 6;
        id.w = (rbx * WP_ + lty) << 6;
        idx_s[n * 64 + m] = id;
        wgt_s[n * 64 + m] = g;
    }
    __syncthreads();

    const float* xpb = g_xp + (size_t)b * HWP_ * C_;
    const int lane = tid & 31;
    const int wid  = tid >> 5;

    // warp-cooperative gather of chunk n: warp w -> samples w*8..w*8+7
    // lane l -> channels 2l, 2l+1; STS contiguous 256B per sample
#define GATHER_CHUNK(ab, nn)                                                  \
    {                                                                         \
        const float* xc = xpb + 2 * lane;                                     \
        int s0 = (nn) * 64 + wid * 8;                                         \
        _Pragma("unroll")                                                     \
        for (int i = 0; i < 8; i++) {                                         \
            int4 id = idx_s[s0 + i];                                          \
            float4 g = wgt_s[s0 + i];                                         \
            float2 lt = *(const float2*)(xc + id.x);                          \
            float2 rb = *(const float2*)(xc + id.y);                          \
            float2 lb = *(const float2*)(xc + id.z);                          \
            float2 rt = *(const float2*)(xc + id.w);                          \
            float v0 = g.x*lt.x + g.y*rb.x + g.z*lb.x + g.w*rt.x;             \
            float v1 = g.x*lt.y + g.y*rb.y + g.z*lb.y + g.w*rt.y;             \
            *(float2*)((ab) + (wid * 8 + i) * APITCH + 2 * lane) =            \
                make_float2(v0, v1);                                          \
        }                                                                     \
    }

    GATHER_CHUNK(slab, 0)

    int tx = tid & 15, ty = tid >> 4;
    unsigned long long acc[4][4];    // [px][oc], f32x2 = (even-k sum, odd-k sum)
#pragma unroll
    for (int i = 0; i < 4; i++)
#pragma unroll
        for (int j = 0; j < 4; j++) acc[i][j] = 0ull;

    // ---- pipelined chunk loop: gather(n+1) overlaps GEMM(n) ----
    for (int c = 0; c < 9; c++) {
        __syncthreads();

        if (c < 8) {
            float* ab = slab + ((c + 1) & 1) * SLABN;
            GATHER_CHUNK(ab, c + 1)
        }

        const float* ab = slab + (c & 1) * SLABN + (ty * 4) * APITCH;
        const float* wrow = g_wt2 + c * 32 * 128 + tx * 4;
#pragma unroll 4
        for (int kq = 0; kq < 16; kq++) {        // 4 k per iter (2 k-pairs)
            ulonglong2 av[4];
#pragma unroll
            for (int p = 0; p < 4; p++)
                av[p] = *(const ulonglong2*)(ab + p * APITCH + kq * 4);
#pragma unroll
            for (int hh = 0; hh < 2; hh++) {
                const float* wr = wrow + (kq * 2 + hh) * 128;
                ulonglong2 ba = *(const ulonglong2*)(wr);        // oc j0,j1
                ulonglong2 bb = *(const ulonglong2*)(wr + 64);   // oc j2,j3
#pragma unroll
                for (int p = 0; p < 4; p++) {
                    unsigned long long a = hh ? av[p].y : av[p].x;
                    FMA2(acc[p][0], a, ba.x);
                    FMA2(acc[p][1], a, ba.y);
                    FMA2(acc[p][2], a, bb.x);
                    FMA2(acc[p][3], a, bb.y);
                }
            }
        }
    }

    // ---- epilogue: res = lo + hi, stage via smem, coalesced residual ----
    __syncthreads();
    float* sa = slab;  // [oc][m] 64x64 (both buffers dead)
#pragma unroll
    for (int p = 0; p < 4; p++) {
        int m = ty * 4 + p;
#pragma unroll
        for (int j = 0; j < 4; j++) {
            unsigned long long v = acc[p][j];
            float lo = __uint_as_float((unsigned)(v & 0xffffffffull));
            float hi = __uint_as_float((unsigned)(v >> 32));
            sa[(tx * 4 + j) * 64 + m] = lo + hi;
        }
    }
    __syncthreads();

    for (int e = tid; e < 64 * 64; e += 256) {
        int oc = e >> 6, m = e & 63;
        int h = h0 + (m >> 3), w = w0 + (m & 7);
        int gi = ((b * C_ + oc) * H_ + h) * W_ + w;
        out[gi] = x[gi] + sa[e];
    }
}

// ============================================================
extern "C" void kernel_launch(void* const* d_in, const int* in_sizes, int n_in,
                              void* d_out, int out_size) {
    const float* x       = (const float*)d_in[0];
    const float* w_conv1 = (const float*)d_in[1];
    const float* g1 = (const float*)d_in[2];
    const float* b1 = (const float*)d_in[3];
    const float* m1 = (const float*)d_in[4];
    const float* v1 = (const float*)d_in[5];
    const float* w_dw = (const float*)d_in[6];
    const float* g2 = (const float*)d_in[7];
    const float* b2 = (const float*)d_in[8];
    const float* m2 = (const float*)d_in[9];
    const float* v2 = (const float*)d_in[10];
    const float* w_conv2 = (const float*)d_in[11];
    const float* g3 = (const float*)d_in[12];
    const float* b3 = (const float*)d_in[13];
    const float* m3 = (const float*)d_in[14];
    const float* v3 = (const float*)d_in[15];
    const float* w_out = (const float*)d_in[16];
    float* out = (float*)d_out;

    cudaFuncSetAttribute(k3_main, cudaFuncAttributeMaxDynamicSharedMemorySize, K3_SMEM);

    k_padT<<<PAD_BLKS + W0_BLKS, 256>>>(x, w_out);
    k1_conv1<<<PIXT / 256, 256>>>(x, w_conv1, g1, b1, m1, v1);
    k2_offsets<<<128, 256>>>(w_dw, g2, b2, m2, v2, w_conv2, g3, b3, m3, v3);
    k3_main<<<B_ * (H_ / 8) * (W_ / 8), 256, K3_SMEM>>>(x, out);
}

// round 10
// speedup vs baseline: 1.3428x; 1.3428x over previous
#include <cuda_runtime.h>
#include <math.h>
#include <stdint.h>

// Problem constants
#define B_  2
#define C_  64
#define H_  128
#define W_  128
#define HW_ (H_*W_)          // 16384
#define HID 16
#define OFC 18
#define NPT 9
#define KTOT (C_*NPT)        // 576
#define PIXT (B_*HW_)        // 32768
#define HP_  130
#define WP_  130
#define HWP_ (HP_*WP_)       // 16900

// ---- device scratch (no runtime allocation allowed) ----
__device__ float g_f  [B_*HID*HW_];       // offset-branch feature [B,16,H,W]
__device__ float g_off[B_*OFC*HW_];       // offsets               [B,18,H,W]
__device__ float g_wt2[288*128];          // k-pair-packed w_out (see k_padT)
__device__ float g_xp [B_*HWP_*C_ + 8];   // TRANSPOSED padded input [B][130*130][64]

// packed fp32x2 FMA (per-component accumulate: pairs carry adjacent k)
#define FMA2(d,a,b) asm("fma.rn.f32x2 %0, %1, %2, %0;" : "+l"(d) : "l"(a), "l"(b))

__device__ __forceinline__ void cp_async16(uint32_t dst, const void* src) {
    asm volatile("cp.async.ca.shared.global [%0], [%1], 16;" :: "r"(dst), "l"(src));
}
#define CP_COMMIT() asm volatile("cp.async.commit_group;")
#define CP_WAIT0()  asm volatile("cp.async.wait_group 0;")

// ============================================================
// K_padT: zero-pad + TRANSPOSE x into g_xp[b][hw_p][c]
//   tail blocks: pack w_out into g_wt2 (k-pair layout, see R9 comment)
// ============================================================
#define PAD_BLKS (B_*HP_)
#define W0_BLKS  ((KTOT*C_ + 255)/256)
__global__ __launch_bounds__(256)
void k_padT(const float* __restrict__ x, const float* __restrict__ w) {
    int blk = blockIdx.x;
    int tid = threadIdx.x;
    if (blk < PAD_BLKS) {
        __shared__ float ts[WP_ * 65];     // [w][c] pitch 65 (conflict-free)
        int b = blk / HP_, h = blk % HP_;
        if (h >= 1 && h <= H_) {
            const float* xr = x + (size_t)b * C_ * HW_ + (h - 1) * W_;
            for (int e = tid; e < C_ * W_; e += 256) {
                int c = e >> 7, w2 = e & 127;            // coalesced read along w
                ts[(w2 + 1) * 65 + c] = xr[c * HW_ + w2];
            }
            if (tid < 2 * C_) {                          // border columns
                int c = tid & 63, side = tid >> 6;
                ts[(side ? (WP_ - 1) * 65 : 0) + c] = 0.f;
            }
        } else {
            for (int e = tid; e < WP_ * C_; e += 256) {
                int w2 = e >> 6, c = e & 63;
                ts[w2 * 65 + c] = 0.f;
            }
        }
        __syncthreads();
        float* dst = g_xp + ((size_t)b * HP_ + h) * WP_ * C_;
        for (int e = tid; e < WP_ * C_; e += 256) {
            int w2 = e >> 6, c = e & 63;
            dst[e] = ts[w2 * 65 + c];                    // coalesced write along c
        }
    } else {
        int t = (blk - PAD_BLKS) * 256 + tid;
        if (t < KTOT * C_) {
            int oc = t / KTOT, r = t - oc * KTOT;        // r = ci*9 + n
            int ci = r / 9, n = r - ci * 9;
            int kp = n * 32 + (ci >> 1);
            int q  = ci & 1;
            int tq = oc >> 2, j = oc & 3;
            int col = (j < 2) ? (tq * 4 + j * 2 + q)
                              : (64 + tq * 4 + (j - 2) * 2 + q);
            g_wt2[kp * 128 + col] = w[t];
        }
    }
}

// ============================================================
// K1: f = relu(bn(conv1x1_{64->16}(x)))
// ============================================================
__global__ void k1_conv1(const float* __restrict__ x,
                         const float* __restrict__ w1,
                         const float* __restrict__ g1,
                         const float* __restrict__ b1,
                         const float* __restrict__ m1,
                         const float* __restrict__ v1) {
    __shared__ float ws[C_][HID];
    __shared__ float inv_s[HID], beta_s[HID];
    int tid = threadIdx.x;
    for (int e = tid; e < HID * C_; e += 256) {
        int o = e / C_, c = e % C_;
        ws[c][o] = w1[e];
    }
    if (tid < HID) {
        float inv = g1[tid] * rsqrtf(v1[tid] + 1e-5f);
        inv_s[tid] = inv;
        beta_s[tid] = b1[tid] - m1[tid] * inv;
    }
    __syncthreads();

    int p = blockIdx.x * 256 + tid;
    int b = p >> 14, hw = p & (HW_ - 1);
    const float* xb = x + (size_t)b * C_ * HW_ + hw;

    float acc[HID];
#pragma unroll
    for (int o = 0; o < HID; o++) acc[o] = 0.f;
    for (int c = 0; c < C_; c++) {
        float xv = xb[c * HW_];
#pragma unroll
        for (int o = 0; o < HID; o++) acc[o] += ws[c][o] * xv;
    }
    float* fb = g_f + (size_t)b * HID * HW_ + hw;
#pragma unroll
    for (int o = 0; o < HID; o++)
        fb[o * HW_] = fmaxf(acc[o] * inv_s[o] + beta_s[o], 0.f);
}

// ============================================================
// K2 (tiled): off = relu(bn3(1x1( relu(bn2(3x3(f))) )))
// ============================================================
__global__ __launch_bounds__(256)
void k2_offsets(const float* __restrict__ wdw,
                const float* __restrict__ g2, const float* __restrict__ b2,
                const float* __restrict__ m2, const float* __restrict__ v2,
                const float* __restrict__ wc2,
                const float* __restrict__ g3, const float* __restrict__ b3,
                const float* __restrict__ m3, const float* __restrict__ v3) {
    __shared__ float fs[HID * 18 * 18];
    __shared__ float wdw_s[OFC * HID * 9];
    __shared__ float wc2_s[OFC * OFC];
    __shared__ float inv2_s[OFC], beta2_s[OFC], inv3_s[OFC], beta3_s[OFC];
    int tid = threadIdx.x;

    int blk = blockIdx.x;
    int b = blk >> 6, t = blk & 63;
    int h0 = (t >> 3) << 4, w0 = (t & 7) << 4;

    for (int e = tid; e < OFC * HID * 9; e += 256) wdw_s[e] = wdw[e];
    for (int e = tid; e < OFC * OFC; e += 256)     wc2_s[e] = wc2[e];
    if (tid < OFC) {
        float i2 = g2[tid] * rsqrtf(v2[tid] + 1e-5f);
        inv2_s[tid] = i2; beta2_s[tid] = b2[tid] - m2[tid] * i2;
        float i3 = g3[tid] * rsqrtf(v3[tid] + 1e-5f);
        inv3_s[tid] = i3; beta3_s[tid] = b3[tid] - m3[tid] * i3;
    }

    const float* fb = g_f + (size_t)b * HID * HW_;
    for (int e = tid; e < HID * 324; e += 256) {
        int ci = e / 324, r = e - ci * 324;
        int hh = r / 18, ww = r - hh * 18;
        int h = h0 - 1 + hh, w = w0 - 1 + ww;
        float v = 0.f;
        if (h >= 0 && h < H_ && w >= 0 && w < W_)
            v = fb[ci * HW_ + h * W_ + w];
        fs[e] = v;
    }
    __syncthreads();

    int ty2 = tid >> 4, tx2 = tid & 15;
    float acc[OFC];
#pragma unroll
    for (int o = 0; o < OFC; o++) acc[o] = 0.f;

    for (int ci = 0; ci < HID; ci++) {
        float fv[9];
        const float* fsc = fs + ci * 324;
#pragma unroll
        for (int dh = 0; dh < 3; dh++)
#pragma unroll
            for (int dw = 0; dw < 3; dw++)
                fv[dh * 3 + dw] = fsc[(ty2 + dh) * 18 + (tx2 + dw)];
        const float* wp = wdw_s + ci * 9;
#pragma unroll
        for (int o = 0; o < OFC; o++) {
            const float* wo = wp + o * (HID * 9);
            float a = acc[o];
#pragma unroll
            for (int k = 0; k < 9; k++) a += wo[k] * fv[k];
            acc[o] = a;
        }
    }
    float tv[OFC];
#pragma unroll
    for (int o = 0; o < OFC; o++)
        tv[o] = fmaxf(acc[o] * inv2_s[o] + beta2_s[o], 0.f);

    int h = h0 + ty2, w = w0 + tx2;
    float* op = g_off + (size_t)b * OFC * HW_ + h * W_ + w;
#pragma unroll
    for (int o2 = 0; o2 < OFC; o2++) {
        float a = 0.f;
#pragma unroll
        for (int o = 0; o < OFC; o++) a += wc2_s[o2 * OFC + o] * tv[o];
        op[o2 * HW_] = fmaxf(a * inv3_s[o2] + beta3_s[o2], 0.f);
    }
}

// ============================================================
// K3: fused bilinear sampler + SGEMM, k-paired f32x2, B staged in smem
//   chunk = sampling point n (9 chunks of 64 k = 64 channels)
//   B chunk (16KB) double-buffered via cp.async; slab double-buffered
// ============================================================
#define APITCH 68
#define SLABN (64*APITCH)
#define BCH   4096                         // floats per B chunk (32 kp x 128)
#define SMEM_SLAB 18432
#define SMEM_B    (SMEM_SLAB + 2*SLABN*4)  // 53248
#define K3_SMEM   (SMEM_B + 2*BCH*4)       // 86016

__global__ __launch_bounds__(256, 2)
void k3_main(const float* __restrict__ x, float* __restrict__ out) {
    extern __shared__ char smem[];
    int4*   idx_s = (int4*)smem;                   // [576] (n*64+m), premult by 64
    float4* wgt_s = (float4*)(smem + 9216);        // [576]
    float*  slab  = (float*)(smem + SMEM_SLAB);    // [2][64][APITCH]
    float*  bsm   = (float*)(smem + SMEM_B);       // [2][4096]

    int tid = threadIdx.x;
    int blk = blockIdx.x;
    int b = blk >> 8;
    int tile = blk & 255;
    int h0 = (tile >> 4) << 3;
    int w0 = (tile & 15) << 3;

    // ---- bilinear metadata: 64 px x 9 pts ----
    const float* offp = g_off + (size_t)b * OFC * HW_;
    for (int e = tid; e < 64 * NPT; e += 256) {
        int m = e / NPT, n = e - m * NPT;
        int h = h0 + (m >> 3), w = w0 + (m & 7);
        int hw = h * W_ + w;
        float offx = offp[n * HW_ + hw];
        float offy = offp[(NPT + n) * HW_ + hw];
        float px = (float)(h + 1) + (float)(n / 3 - 1) + offx;
        float py = (float)(w + 1) + (float)(n % 3 - 1) + offy;
        float flx = floorf(px), fly = floorf(py);
        float qltx = fminf(fmaxf(flx, 0.f), 129.f);
        float qlty = fminf(fmaxf(fly, 0.f), 129.f);
        float qrbx = fminf(fmaxf(flx + 1.f, 0.f), 129.f);
        float qrby = fminf(fmaxf(fly + 1.f, 0.f), 129.f);
        px = fminf(fmaxf(px, 0.f), 129.f);
        py = fminf(fmaxf(py, 0.f), 129.f);
        float gxl = 1.f + qltx - px, gxr = 1.f - qrbx + px;
        float gyl = 1.f + qlty - py, gyr = 1.f - qrby + py;
        float4 g;
        g.x = gxl * gyl; g.y = gxr * gyr; g.z = gxl * gyr; g.w = gxr * gyl;
        int ltx = (int)qltx, lty = (int)qlty, rbx = (int)qrbx, rby = (int)qrby;
        int4 id;
        id.x = (ltx * WP_ + lty) << 6;    // premultiplied by C_=64
        id.y = (rbx * WP_ + rby) << 6;
        id.z = (ltx * WP_ + rby) << 6;
        id.w = (rbx * WP_ + lty) << 6;
        idx_s[n * 64 + m] = id;
        wgt_s[n * 64 + m] = g;
    }

    const float* xpb = g_xp + (size_t)b * HWP_ * C_;
    const int lane = tid & 31;
    const int wid  = tid >> 5;

    // B-chunk staging: each thread cp.asyncs 4 x 16B (coalesced)
    uint32_t bsm_u32 = (uint32_t)__cvta_generic_to_shared(bsm);
#define STAGE_B(buf, cc)                                                      \
    {                                                                         \
        const float* src = g_wt2 + (cc) * BCH + tid * 4;                      \
        uint32_t dst = bsm_u32 + (buf) * (BCH*4) + tid * 16;                  \
        cp_async16(dst,          src);                                        \
        cp_async16(dst + 4096,   src + 1024);                                 \
        cp_async16(dst + 8192,   src + 2048);                                 \
        cp_async16(dst + 12288,  src + 3072);                                 \
        CP_COMMIT();                                                          \
    }

    // warp-cooperative gather of chunk n: warp w -> samples w*8..w*8+7
#define GATHER_CHUNK(ab, nn)                                                  \
    {                                                                         \
        const float* xc = xpb + 2 * lane;                                     \
        int s0 = (nn) * 64 + wid * 8;                                         \
        _Pragma("unroll")                                                     \
        for (int i = 0; i < 8; i++) {                                         \
            int4 id = idx_s[s0 + i];                                          \
            float4 g = wgt_s[s0 + i];                                         \
            float2 lt = *(const float2*)(xc + id.x);                          \
            float2 rb = *(const float2*)(xc + id.y);                          \
            float2 lb = *(const float2*)(xc + id.z);                          \
            float2 rt = *(const float2*)(xc + id.w);                          \
            float v0 = g.x*lt.x + g.y*rb.x + g.z*lb.x + g.w*rt.x;             \
            float v1 = g.x*lt.y + g.y*rb.y + g.z*lb.y + g.w*rt.y;             \
            *(float2*)((ab) + (wid * 8 + i) * APITCH + 2 * lane) =            \
                make_float2(v0, v1);                                          \
        }                                                                     \
    }

    STAGE_B(0, 0)
    __syncthreads();           // meta ready (also covers idx/wgt writes)
    GATHER_CHUNK(slab, 0)

    int tx = tid & 15, ty = tid >> 4;
    unsigned long long acc[4][4];    // [px][oc], f32x2 = (even-k, odd-k) partials
#pragma unroll
    for (int i = 0; i < 4; i++)
#pragma unroll
        for (int j = 0; j < 4; j++) acc[i][j] = 0ull;

    // ---- pipelined chunk loop ----
    // order per iter: wait B(c) -> barrier -> issue B(c+1) -> gather(c+1) -> GEMM(c)
    for (int c = 0; c < 9; c++) {
        CP_WAIT0();
        __syncthreads();

        if (c < 8) {
            STAGE_B((c + 1) & 1, c + 1)
            float* ab = slab + ((c + 1) & 1) * SLABN;
            GATHER_CHUNK(ab, c + 1)
        }

        const float* ab = slab + (c & 1) * SLABN + (ty * 4) * APITCH;
        const float* wrow = bsm + (c & 1) * BCH + tx * 4;
#pragma unroll 4
        for (int kq = 0; kq < 16; kq++) {        // 4 k per iter (2 k-pairs)
            ulonglong2 av[4];
#pragma unroll
            for (int p = 0; p < 4; p++)
                av[p] = *(const ulonglong2*)(ab + p * APITCH + kq * 4);
#pragma unroll
            for (int hh = 0; hh < 2; hh++) {
                const float* wr = wrow + (kq * 2 + hh) * 128;
                ulonglong2 ba = *(const ulonglong2*)(wr);        // oc j0,j1
                ulonglong2 bb = *(const ulonglong2*)(wr + 64);   // oc j2,j3
#pragma unroll
                for (int p = 0; p < 4; p++) {
                    unsigned long long a = hh ? av[p].y : av[p].x;
                    FMA2(acc[p][0], a, ba.x);
                    FMA2(acc[p][1], a, ba.y);
                    FMA2(acc[p][2], a, bb.x);
                    FMA2(acc[p][3], a, bb.y);
                }
            }
        }
    }

    // ---- epilogue: res = lo + hi, stage via smem, coalesced residual ----
    __syncthreads();
    float* sa = slab;  // [oc][m] 64x64 (both buffers dead)
#pragma unroll
    for (int p = 0; p < 4; p++) {
        int m = ty * 4 + p;
#pragma unroll
        for (int j = 0; j < 4; j++) {
            unsigned long long v = acc[p][j];
            float lo = __uint_as_float((unsigned)(v & 0xffffffffull));
            float hi = __uint_as_float((unsigned)(v >> 32));
            sa[(tx * 4 + j) * 64 + m] = lo + hi;
        }
    }
    __syncthreads();

    for (int e = tid; e < 64 * 64; e += 256) {
        int oc = e >> 6, m = e & 63;
        int h = h0 + (m >> 3), w = w0 + (m & 7);
        int gi = ((b * C_ + oc) * H_ + h) * W_ + w;
        out[gi] = x[gi] + sa[e];
    }
}

// ============================================================
extern "C" void kernel_launch(void* const* d_in, const int* in_sizes, int n_in,
                              void* d_out, int out_size) {
    const float* x       = (const float*)d_in[0];
    const float* w_conv1 = (const float*)d_in[1];
    const float* g1 = (const float*)d_in[2];
    const float* b1 = (const float*)d_in[3];
    const float* m1 = (const float*)d_in[4];
    const float* v1 = (const float*)d_in[5];
    const float* w_dw = (const float*)d_in[6];
    const float* g2 = (const float*)d_in[7];
    const float* b2 = (const float*)d_in[8];
    const float* m2 = (const float*)d_in[9];
    const float* v2 = (const float*)d_in[10];
    const float* w_conv2 = (const float*)d_in[11];
    const float* g3 = (const float*)d_in[12];
    const float* b3 = (const float*)d_in[13];
    const float* m3 = (const float*)d_in[14];
    const float* v3 = (const float*)d_in[15];
    const float* w_out = (const float*)d_in[16];
    float* out = (float*)d_out;

    cudaFuncSetAttribute(k3_main, cudaFuncAttributeMaxDynamicSharedMemorySize, K3_SMEM);

    k_padT<<<PAD_BLKS + W0_BLKS, 256>>>(x, w_out);
    k1_conv1<<<PIXT / 256, 256>>>(x, w_conv1, g1, b1, m1, v1);
    k2_offsets<<<128, 256>>>(w_dw, g2, b2, m2, v2, w_conv2, g3, b3, m3, v3);
    k3_main<<<B_ * (H_ / 8) * (W_ / 8), 256, K3_SMEM>>>(x, out);
}